// round 1
// baseline (speedup 1.0000x reference)
#include <cuda_runtime.h>
#include <cuda_bf16.h>

// Problem shapes (fixed by the dataset)
#define EMB       512
#define N_NODES   16384
#define N_PAIRS   200000

// Scratch (device globals — no allocation allowed)
__device__ float g_node_mean[N_NODES];
__device__ float g_pair_sum[N_PAIRS];
__device__ float g_pair_cnt[N_PAIRS];
__device__ float g_place_sum[N_NODES];
__device__ float g_place_cnt[N_NODES];

// ---------------------------------------------------------------------------
// K0: zero all accumulators
// ---------------------------------------------------------------------------
__global__ void k_zero() {
    int i = blockIdx.x * blockDim.x + threadIdx.x;
    int stride = gridDim.x * blockDim.x;
    for (int j = i; j < N_PAIRS; j += stride) {
        g_pair_sum[j] = 0.0f;
        g_pair_cnt[j] = 0.0f;
    }
    for (int j = i; j < N_NODES; j += stride) {
        g_place_sum[j] = 0.0f;
        g_place_cnt[j] = 0.0f;
    }
}

// ---------------------------------------------------------------------------
// K1: node_mean[n] = mean(embeddings[n, :])   one warp per row, float4 loads
// ---------------------------------------------------------------------------
__global__ void k_node_mean(const float* __restrict__ emb) {
    int warp_id = (blockIdx.x * blockDim.x + threadIdx.x) >> 5;
    int lane = threadIdx.x & 31;
    if (warp_id >= N_NODES) return;
    const float4* row = reinterpret_cast<const float4*>(emb + (size_t)warp_id * EMB);
    // EMB/4 = 128 float4 per row, 4 per lane
    float s = 0.0f;
    #pragma unroll
    for (int k = 0; k < 4; k++) {
        float4 v = row[lane + 32 * k];
        s += v.x + v.y + v.z + v.w;
    }
    #pragma unroll
    for (int off = 16; off > 0; off >>= 1)
        s += __shfl_down_sync(0xffffffffu, s, off);
    if (lane == 0)
        g_node_mean[warp_id] = s * (1.0f / EMB);
}

// ---------------------------------------------------------------------------
// K2: dst-entry scatter — each dst entry contributes
//     node_mean[dst_node] / (3*(ndst[e]+1)) to pair_sum[event_pair[e]]
// ---------------------------------------------------------------------------
__global__ void k_dst_scatter(const int* __restrict__ dst_event,
                              const int* __restrict__ dst_node,
                              const int* __restrict__ event_pair,
                              const int* __restrict__ event_ndst,
                              int n_dst) {
    int i = blockIdx.x * blockDim.x + threadIdx.x;
    int stride = gridDim.x * blockDim.x;
    for (; i < n_dst; i += stride) {
        int e = dst_event[i];
        int p = event_pair[e];
        float nd = (float)event_ndst[e];
        float v = g_node_mean[dst_node[i]] * (1.0f / 3.0f) / (nd + 1.0f);
        atomicAdd(&g_pair_sum[p], v);
    }
}

// ---------------------------------------------------------------------------
// K3: event scatter — (node_mean[place] + node_mean[src]) / 3 into pair_sum,
//     count into pair_cnt
// ---------------------------------------------------------------------------
__global__ void k_event_scatter(const int* __restrict__ event_pair,
                                const int* __restrict__ event_src,
                                const int* __restrict__ pair_place,
                                int n_events) {
    int i = blockIdx.x * blockDim.x + threadIdx.x;
    int stride = gridDim.x * blockDim.x;
    for (; i < n_events; i += stride) {
        int p = event_pair[i];
        int place = pair_place[p];
        float v = (g_node_mean[place] + g_node_mean[event_src[i]]) * (1.0f / 3.0f);
        atomicAdd(&g_pair_sum[p], v);
        atomicAdd(&g_pair_cnt[p], 1.0f);
    }
}

// ---------------------------------------------------------------------------
// K4: pair -> place reduction
// ---------------------------------------------------------------------------
__global__ void k_pair_to_place(const int* __restrict__ pair_place) {
    int p = blockIdx.x * blockDim.x + threadIdx.x;
    if (p >= N_PAIRS) return;
    float c = g_pair_cnt[p];
    if (c > 0.0f) {
        float pm = g_pair_sum[p] / c;
        int pl = pair_place[p];
        atomicAdd(&g_place_sum[pl], pm);
        atomicAdd(&g_place_cnt[pl], 1.0f);
    }
}

// ---------------------------------------------------------------------------
// K5: output broadcast — row n filled with place_mean[n], 3*EMB columns
//     one block per row, float4 stores
// ---------------------------------------------------------------------------
__global__ void k_fill_out(float* __restrict__ out) {
    int row = blockIdx.x;
    float c = g_place_cnt[row];
    float v = (c > 0.0f) ? (g_place_sum[row] / c) : 0.0f;
    float4 v4 = make_float4(v, v, v, v);
    float4* o = reinterpret_cast<float4*>(out + (size_t)row * (3 * EMB));
    // 3*EMB/4 = 384 float4; 128 threads x 3 each
    int t = threadIdx.x;
    #pragma unroll
    for (int k = 0; k < 3; k++)
        o[t + 128 * k] = v4;
}

// ---------------------------------------------------------------------------
extern "C" void kernel_launch(void* const* d_in, const int* in_sizes, int n_in,
                              void* d_out, int out_size) {
    const float* embeddings = (const float*)d_in[0];
    const int* pair_place   = (const int*)d_in[1];
    const int* event_pair   = (const int*)d_in[2];
    const int* event_src    = (const int*)d_in[3];
    const int* event_ndst   = (const int*)d_in[4];
    const int* dst_event    = (const int*)d_in[5];
    const int* dst_node     = (const int*)d_in[6];
    float* out = (float*)d_out;

    int n_events = in_sizes[2];
    int n_dst = in_sizes[5];

    k_zero<<<256, 256>>>();
    k_node_mean<<<(N_NODES * 32 + 255) / 256, 256>>>(embeddings);
    k_dst_scatter<<<(n_dst + 255) / 256, 256>>>(dst_event, dst_node, event_pair,
                                                event_ndst, n_dst);
    k_event_scatter<<<(n_events + 255) / 256, 256>>>(event_pair, event_src,
                                                     pair_place, n_events);
    k_pair_to_place<<<(N_PAIRS + 255) / 256, 256>>>(pair_place);
    k_fill_out<<<N_NODES, 128>>>(out);
}

// round 2
// speedup vs baseline: 1.3963x; 1.3963x over previous
#include <cuda_runtime.h>
#include <cuda_bf16.h>

#define EMB       512
#define N_NODES   16384
#define N_PAIRS   200000

// Scratch (device globals — no allocation allowed)
__device__ float  g_node_mean[N_NODES];
__device__ float2 g_pair[N_PAIRS];    // x = sum of (nm[src] + dst_term), y = event count
__device__ float2 g_place[N_NODES];   // x = sum of pair_means, y = pair count

// Vectorized float2 reduction (one L2 atomic op for sum+count)
__device__ __forceinline__ void red_add_v2(float2* addr, float a, float b) {
    asm volatile("red.global.add.v2.f32 [%0], {%1, %2};"
                 :: "l"(addr), "f"(a), "f"(b) : "memory");
}

// ---------------------------------------------------------------------------
// K1: zero accumulators + node_mean (one warp per row, float4 loads)
// grid = 2048 blocks x 256 thr = 16384 warps
// ---------------------------------------------------------------------------
__global__ void k_mean_zero(const float* __restrict__ emb) {
    int tid = blockIdx.x * blockDim.x + threadIdx.x;
    int stride = gridDim.x * blockDim.x;
    for (int j = tid; j < N_PAIRS; j += stride) g_pair[j] = make_float2(0.f, 0.f);
    for (int j = tid; j < N_NODES; j += stride) g_place[j] = make_float2(0.f, 0.f);

    int row = tid >> 5;
    int lane = tid & 31;
    if (row >= N_NODES) return;
    const float4* r = reinterpret_cast<const float4*>(emb + (size_t)row * EMB);
    float s = 0.0f;
    #pragma unroll
    for (int k = 0; k < 4; k++) {
        float4 v = r[lane + 32 * k];
        s += (v.x + v.y) + (v.z + v.w);
    }
    #pragma unroll
    for (int off = 16; off > 0; off >>= 1)
        s += __shfl_down_sync(0xffffffffu, s, off);
    if (lane == 0)
        g_node_mean[row] = s * (1.0f / EMB);
}

// ---------------------------------------------------------------------------
// K2: fused scatter.
//  events:  pair[p] += {nm[src], 1}           (one v2 red per event)
//  dsts:    pair[p].x += nm[dst]/(nd+1)       (dst_event sorted -> monotonic gathers)
// ---------------------------------------------------------------------------
__global__ void k_scatter(const int* __restrict__ event_pair,
                          const int* __restrict__ event_src,
                          const int* __restrict__ event_ndst,
                          const int* __restrict__ dst_event,
                          const int* __restrict__ dst_node,
                          int n_events, int n_dst) {
    int tid = blockIdx.x * blockDim.x + threadIdx.x;
    int stride = gridDim.x * blockDim.x;

    for (int i = tid; i < n_events; i += stride) {
        int p = event_pair[i];
        float v = __ldg(&g_node_mean[event_src[i]]);
        red_add_v2(&g_pair[p], v, 1.0f);
    }

    for (int i = tid; i < n_dst; i += stride) {
        int e = dst_event[i];                 // sorted, coalesced
        int p = __ldg(&event_pair[e]);        // monotonic -> ~coalesced
        float nd = (float)__ldg(&event_ndst[e]);
        float v = __ldg(&g_node_mean[dst_node[i]]) / (nd + 1.0f);
        atomicAdd(&g_pair[p].x, v);
    }
}

// ---------------------------------------------------------------------------
// K3: pair -> place.  pair_mean = (pair_sum/cnt + nm[place]) / 3
// ---------------------------------------------------------------------------
__global__ void k_pair_to_place(const int* __restrict__ pair_place) {
    int p = blockIdx.x * blockDim.x + threadIdx.x;
    if (p >= N_PAIRS) return;
    float2 a = g_pair[p];
    if (a.y > 0.0f) {
        int pl = pair_place[p];
        float pm = (a.x / a.y + __ldg(&g_node_mean[pl])) * (1.0f / 3.0f);
        red_add_v2(&g_place[pl], pm, 1.0f);
    }
}

// ---------------------------------------------------------------------------
// K4: broadcast fill — row n = place_mean[n] across 3*EMB cols (float4 stores)
// ---------------------------------------------------------------------------
__global__ void k_fill_out(float* __restrict__ out) {
    int row = blockIdx.x;
    float2 a = g_place[row];
    float v = (a.y > 0.0f) ? (a.x / a.y) : 0.0f;
    float4 v4 = make_float4(v, v, v, v);
    float4* o = reinterpret_cast<float4*>(out + (size_t)row * (3 * EMB));
    int t = threadIdx.x;
    #pragma unroll
    for (int k = 0; k < 3; k++)
        o[t + 128 * k] = v4;
}

// ---------------------------------------------------------------------------
extern "C" void kernel_launch(void* const* d_in, const int* in_sizes, int n_in,
                              void* d_out, int out_size) {
    const float* embeddings = (const float*)d_in[0];
    const int* pair_place   = (const int*)d_in[1];
    const int* event_pair   = (const int*)d_in[2];
    const int* event_src    = (const int*)d_in[3];
    const int* event_ndst   = (const int*)d_in[4];
    const int* dst_event    = (const int*)d_in[5];
    const int* dst_node     = (const int*)d_in[6];
    float* out = (float*)d_out;

    int n_events = in_sizes[2];
    int n_dst = in_sizes[5];

    k_mean_zero<<<(N_NODES * 32) / 256, 256>>>(embeddings);
    k_scatter<<<(n_events + 255) / 256, 256>>>(event_pair, event_src, event_ndst,
                                               dst_event, dst_node, n_events, n_dst);
    k_pair_to_place<<<(N_PAIRS + 255) / 256, 256>>>(pair_place);
    k_fill_out<<<N_NODES, 128>>>(out);
}

// round 3
// speedup vs baseline: 1.4076x; 1.0081x over previous
#include <cuda_runtime.h>
#include <cuda_bf16.h>

#define EMB       512
#define N_NODES   16384
#define N_PAIRS   200000
#define MAX_EVENTS 1000000

// Scratch (device globals — no allocation allowed)
__device__ float  g_node_mean[N_NODES];
__device__ float2 g_pair[N_PAIRS];        // x = sum of per-event scalars, y = event count
__device__ float2 g_place[N_NODES];       // x = sum of pair_means, y = pair count
__device__ int    g_evt_off[MAX_EVENTS];  // start index of each event's dst entries

// Vectorized float2 reduction (one L2 atomic op for sum+count)
__device__ __forceinline__ void red_add_v2(float2* addr, float a, float b) {
    asm volatile("red.global.add.v2.f32 [%0], {%1, %2};"
                 :: "l"(addr), "f"(a), "f"(b) : "memory");
}

// ---------------------------------------------------------------------------
// K1 (fused, all independent):
//   - zero pair/place accumulators
//   - node_mean[n] = mean(embeddings[n,:])    (one warp per row, float4)
//   - evt_off[e] = first dst index of event e (dst_event is sorted)
// grid = 2048 x 256  (16384 warps)
// ---------------------------------------------------------------------------
__global__ void k_prep(const float* __restrict__ emb,
                       const int* __restrict__ dst_event,
                       int n_dst) {
    int tid = blockIdx.x * blockDim.x + threadIdx.x;
    int stride = gridDim.x * blockDim.x;

    for (int j = tid; j < N_PAIRS; j += stride) g_pair[j] = make_float2(0.f, 0.f);
    for (int j = tid; j < N_NODES; j += stride) g_place[j] = make_float2(0.f, 0.f);

    for (int i = tid; i < n_dst; i += stride) {
        int e = dst_event[i];
        if (i == 0 || dst_event[i - 1] != e)
            g_evt_off[e] = i;
    }

    int row = tid >> 5;
    int lane = tid & 31;
    const float4* r = reinterpret_cast<const float4*>(emb + (size_t)row * EMB);
    float s = 0.0f;
    #pragma unroll
    for (int k = 0; k < 4; k++) {
        float4 v = r[lane + 32 * k];
        s += (v.x + v.y) + (v.z + v.w);
    }
    #pragma unroll
    for (int off = 16; off > 0; off >>= 1)
        s += __shfl_down_sync(0xffffffffu, s, off);
    if (lane == 0)
        g_node_mean[row] = s * (1.0f / EMB);
}

// ---------------------------------------------------------------------------
// K2: one thread per event; single red.v2 per event.
//   contribution = nm[src] + (sum over event's dst entries of nm[dst])/(nd+1)
// ---------------------------------------------------------------------------
__global__ void k_event_scatter(const int* __restrict__ event_pair,
                                const int* __restrict__ event_src,
                                const int* __restrict__ event_ndst,
                                const int* __restrict__ dst_node,
                                int n_events) {
    int e = blockIdx.x * blockDim.x + threadIdx.x;
    if (e >= n_events) return;

    int p   = event_pair[e];
    int nd  = event_ndst[e];
    int off = g_evt_off[e];

    float dsum = 0.0f;
    #pragma unroll 4
    for (int j = 0; j < nd; j++)
        dsum += __ldg(&g_node_mean[dst_node[off + j]]);

    float v = __ldg(&g_node_mean[event_src[e]]) + dsum / ((float)nd + 1.0f);
    red_add_v2(&g_pair[p], v, 1.0f);
}

// ---------------------------------------------------------------------------
// K3: pair -> place.  pair_mean = (pair_sum/cnt + nm[place]) / 3
// ---------------------------------------------------------------------------
__global__ void k_pair_to_place(const int* __restrict__ pair_place) {
    int p = blockIdx.x * blockDim.x + threadIdx.x;
    if (p >= N_PAIRS) return;
    float2 a = g_pair[p];
    if (a.y > 0.0f) {
        int pl = pair_place[p];
        float pm = (a.x / a.y + __ldg(&g_node_mean[pl])) * (1.0f / 3.0f);
        red_add_v2(&g_place[pl], pm, 1.0f);
    }
}

// ---------------------------------------------------------------------------
// K4: broadcast fill — one warp per row, 12 independent STG.128 per lane
// grid = 2048 x 256 (16384 warps = one per row)
// ---------------------------------------------------------------------------
__global__ void k_fill_out(float* __restrict__ out) {
    int tid = blockIdx.x * blockDim.x + threadIdx.x;
    int row = tid >> 5;
    int lane = tid & 31;
    float2 a = g_place[row];          // same addr across warp -> broadcast
    float v = (a.y > 0.0f) ? (a.x / a.y) : 0.0f;
    float4 v4 = make_float4(v, v, v, v);
    float4* o = reinterpret_cast<float4*>(out + (size_t)row * (3 * EMB));
    #pragma unroll
    for (int k = 0; k < 12; k++)
        o[lane + 32 * k] = v4;
}

// ---------------------------------------------------------------------------
extern "C" void kernel_launch(void* const* d_in, const int* in_sizes, int n_in,
                              void* d_out, int out_size) {
    const float* embeddings = (const float*)d_in[0];
    const int* pair_place   = (const int*)d_in[1];
    const int* event_pair   = (const int*)d_in[2];
    const int* event_src    = (const int*)d_in[3];
    const int* event_ndst   = (const int*)d_in[4];
    const int* dst_event    = (const int*)d_in[5];
    const int* dst_node     = (const int*)d_in[6];
    float* out = (float*)d_out;

    int n_events = in_sizes[2];
    int n_dst = in_sizes[5];

    k_prep<<<2048, 256>>>(embeddings, dst_event, n_dst);
    k_event_scatter<<<(n_events + 255) / 256, 256>>>(event_pair, event_src,
                                                     event_ndst, dst_node, n_events);
    k_pair_to_place<<<(N_PAIRS + 255) / 256, 256>>>(pair_place);
    k_fill_out<<<2048, 256>>>(out);
}

// round 4
// speedup vs baseline: 1.5175x; 1.0781x over previous
#include <cuda_runtime.h>
#include <cuda_bf16.h>

#define EMB       512
#define N_NODES   16384
#define N_PAIRS   200000
#define MAX_EVENTS 1000000

// Scratch (device globals — no allocation allowed)
__device__ float  g_node_mean[N_NODES];
__device__ float2 g_pair[N_PAIRS];        // x = sum of per-event scalars, y = event count
__device__ float2 g_place[N_NODES];       // x = sum of pair_means, y = pair count
__device__ int    g_evt_off[MAX_EVENTS];  // start index of each event's dst entries

// Vectorized float2 reduction (one L2 atomic op for sum+count)
__device__ __forceinline__ void red_add_v2(float2* addr, float a, float b) {
    asm volatile("red.global.add.v2.f32 [%0], {%1, %2};"
                 :: "l"(addr), "f"(a), "f"(b) : "memory");
}

// ---------------------------------------------------------------------------
// K1 (fused, independent work):
//   - zero pair/place accumulators
//   - node_mean[n] = mean(embeddings[n,:])    (one warp per row, float4)
//   - evt_off[e] = first dst index of event e (dst_event is sorted)
// grid = 2048 x 256  (16384 warps)
// ---------------------------------------------------------------------------
__global__ void k_prep(const float* __restrict__ emb,
                       const int* __restrict__ dst_event,
                       int n_dst) {
    int tid = blockIdx.x * blockDim.x + threadIdx.x;
    int stride = gridDim.x * blockDim.x;

    for (int j = tid; j < N_PAIRS; j += stride) g_pair[j] = make_float2(0.f, 0.f);
    for (int j = tid; j < N_NODES; j += stride) g_place[j] = make_float2(0.f, 0.f);

    for (int i = tid; i < n_dst; i += stride) {
        int e = dst_event[i];
        if (i == 0 || dst_event[i - 1] != e)
            g_evt_off[e] = i;
    }

    int row = tid >> 5;
    int lane = tid & 31;
    const float4* r = reinterpret_cast<const float4*>(emb + (size_t)row * EMB);
    float s = 0.0f;
    #pragma unroll
    for (int k = 0; k < 4; k++) {
        float4 v = r[lane + 32 * k];
        s += (v.x + v.y) + (v.z + v.w);
    }
    #pragma unroll
    for (int off = 16; off > 0; off >>= 1)
        s += __shfl_down_sync(0xffffffffu, s, off);
    if (lane == 0)
        g_node_mean[row] = s * (1.0f / EMB);
}

// ---------------------------------------------------------------------------
// K2: event scatter with node_mean staged in shared memory.
//   grid-stride, 444 blocks x 512 thr, 64KB dyn smem per block.
//   contribution = nm[src] + (sum of nm[dst over event's entries])/(nd+1)
//   one red.v2 per event.
// ---------------------------------------------------------------------------
__global__ void k_event_scatter(const int* __restrict__ event_pair,
                                const int* __restrict__ event_src,
                                const int* __restrict__ event_ndst,
                                const int* __restrict__ dst_node,
                                int n_events) {
    extern __shared__ float s_nm[];   // N_NODES floats = 64KB
    // Stage the table: 512 threads x 8 float4 = 16384 floats
    {
        const float4* src = reinterpret_cast<const float4*>(g_node_mean);
        float4* dst = reinterpret_cast<float4*>(s_nm);
        int t = threadIdx.x;
        #pragma unroll
        for (int k = 0; k < N_NODES / 4 / 512; k++)
            dst[t + 512 * k] = src[t + 512 * k];
    }
    __syncthreads();

    int stride = gridDim.x * blockDim.x;
    for (int e = blockIdx.x * blockDim.x + threadIdx.x; e < n_events; e += stride) {
        int p   = event_pair[e];
        int nd  = event_ndst[e];
        int off = g_evt_off[e];

        // nd in [1,4]: predicated fixed-trip loop, independent smem gathers
        float dsum = 0.0f;
        #pragma unroll
        for (int j = 0; j < 4; j++) {
            float v = (j < nd) ? s_nm[__ldg(&dst_node[off + j])] : 0.0f;
            dsum += v;
        }

        float val = s_nm[event_src[e]] + dsum / ((float)nd + 1.0f);
        red_add_v2(&g_pair[p], val, 1.0f);
    }
}

// ---------------------------------------------------------------------------
// K3: pair -> place.  pair_mean = (pair_sum/cnt + nm[place]) / 3
// ---------------------------------------------------------------------------
__global__ void k_pair_to_place(const int* __restrict__ pair_place) {
    int p = blockIdx.x * blockDim.x + threadIdx.x;
    if (p >= N_PAIRS) return;
    float2 a = g_pair[p];
    if (a.y > 0.0f) {
        int pl = pair_place[p];
        float pm = (a.x / a.y + __ldg(&g_node_mean[pl])) * (1.0f / 3.0f);
        red_add_v2(&g_place[pl], pm, 1.0f);
    }
}

// ---------------------------------------------------------------------------
// K4: broadcast fill — one warp per row, 12 independent STG.128 per lane.
//     This sits at the chip STG/LTS cap (~6.1TB/s); at its floor.
// ---------------------------------------------------------------------------
__global__ void k_fill_out(float* __restrict__ out) {
    int tid = blockIdx.x * blockDim.x + threadIdx.x;
    int row = tid >> 5;
    int lane = tid & 31;
    float2 a = g_place[row];          // same addr across warp -> broadcast
    float v = (a.y > 0.0f) ? (a.x / a.y) : 0.0f;
    float4 v4 = make_float4(v, v, v, v);
    float4* o = reinterpret_cast<float4*>(out + (size_t)row * (3 * EMB));
    #pragma unroll
    for (int k = 0; k < 12; k++)
        o[lane + 32 * k] = v4;
}

// ---------------------------------------------------------------------------
extern "C" void kernel_launch(void* const* d_in, const int* in_sizes, int n_in,
                              void* d_out, int out_size) {
    const float* embeddings = (const float*)d_in[0];
    const int* pair_place   = (const int*)d_in[1];
    const int* event_pair   = (const int*)d_in[2];
    const int* event_src    = (const int*)d_in[3];
    const int* event_ndst   = (const int*)d_in[4];
    const int* dst_event    = (const int*)d_in[5];
    const int* dst_node     = (const int*)d_in[6];
    float* out = (float*)d_out;

    int n_events = in_sizes[2];
    int n_dst = in_sizes[5];

    const int SMEM = N_NODES * (int)sizeof(float);   // 64KB
    cudaFuncSetAttribute(k_event_scatter,
                         cudaFuncAttributeMaxDynamicSharedMemorySize, SMEM);

    k_prep<<<2048, 256>>>(embeddings, dst_event, n_dst);
    k_event_scatter<<<444, 512, SMEM>>>(event_pair, event_src, event_ndst,
                                        dst_node, n_events);
    k_pair_to_place<<<(N_PAIRS + 255) / 256, 256>>>(pair_place);
    k_fill_out<<<2048, 256>>>(out);
}

// round 5
// speedup vs baseline: 1.6593x; 1.0935x over previous
#include <cuda_runtime.h>
#include <cuda_bf16.h>

#define EMB       512
#define N_NODES   16384
#define N_PAIRS   200000
#define MAX_EVENTS 1000000

// Scratch (device globals — no allocation allowed)
__device__ float  g_node_mean[N_NODES];
__device__ float2 g_pair[N_PAIRS];        // x = sum of per-event scalars, y = event count
__device__ float2 g_place[N_NODES];       // x = sum of pair_means, y = pair count
__device__ int    g_evt_off[MAX_EVENTS];  // start index of each event's dst entries

// Vectorized float2 reduction (one L2 atomic op for sum+count)
__device__ __forceinline__ void red_add_v2(float2* addr, float a, float b) {
    asm volatile("red.global.add.v2.f32 [%0], {%1, %2};"
                 :: "l"(addr), "f"(a), "f"(b) : "memory");
}

// ---------------------------------------------------------------------------
// K1 (fused, independent work):
//   - zero pair/place accumulators
//   - node_mean[n] = mean(embeddings[n,:])    (one warp per row, float4)
//   - evt_off[e] = first dst index of event e (dst_event sorted; int4 scan)
// grid = 2048 x 256  (16384 warps)
// ---------------------------------------------------------------------------
__global__ void k_prep(const float* __restrict__ emb,
                       const int* __restrict__ dst_event,
                       int n_dst) {
    int tid = blockIdx.x * blockDim.x + threadIdx.x;
    int stride = gridDim.x * blockDim.x;

    for (int j = tid; j < N_PAIRS; j += stride) g_pair[j] = make_float2(0.f, 0.f);
    for (int j = tid; j < N_NODES; j += stride) g_place[j] = make_float2(0.f, 0.f);

    // boundary scan, 4 elements per thread via LDG.128
    int n_grp = (n_dst + 3) >> 2;
    const int4* de4 = reinterpret_cast<const int4*>(dst_event);
    for (int g = tid; g < n_grp; g += stride) {
        int base = g << 2;
        if (base + 3 < n_dst) {
            int4 v = de4[g];
            int prev = (base == 0) ? -1 : __ldg(&dst_event[base - 1]);
            if (v.x != prev) g_evt_off[v.x] = base;
            if (v.y != v.x)  g_evt_off[v.y] = base + 1;
            if (v.z != v.y)  g_evt_off[v.z] = base + 2;
            if (v.w != v.z)  g_evt_off[v.w] = base + 3;
        } else {
            for (int i = base; i < n_dst; i++) {
                int e = dst_event[i];
                int prev = (i == 0) ? -1 : dst_event[i - 1];
                if (e != prev) g_evt_off[e] = i;
            }
        }
    }

    int row = tid >> 5;
    int lane = tid & 31;
    const float4* r = reinterpret_cast<const float4*>(emb + (size_t)row * EMB);
    float s = 0.0f;
    #pragma unroll
    for (int k = 0; k < 4; k++) {
        float4 v = r[lane + 32 * k];
        s += (v.x + v.y) + (v.z + v.w);
    }
    #pragma unroll
    for (int off = 16; off > 0; off >>= 1)
        s += __shfl_down_sync(0xffffffffu, s, off);
    if (lane == 0)
        g_node_mean[row] = s * (1.0f / EMB);
}

// ---------------------------------------------------------------------------
// K2: event scatter with node_mean staged in shared memory.
//   296 blocks x 1024 thr (2 blocks/SM), 64KB dyn smem per block.
//   contribution = nm[src] + (sum of nm[dst over event's entries])/(nd+1)
//   one red.v2 per event.
// ---------------------------------------------------------------------------
__global__ void __launch_bounds__(1024, 2)
k_event_scatter(const int* __restrict__ event_pair,
                const int* __restrict__ event_src,
                const int* __restrict__ event_ndst,
                const int* __restrict__ dst_node,
                int n_events) {
    extern __shared__ float s_nm[];   // N_NODES floats = 64KB
    {
        const float4* src = reinterpret_cast<const float4*>(g_node_mean);
        float4* dst = reinterpret_cast<float4*>(s_nm);
        int t = threadIdx.x;
        #pragma unroll
        for (int k = 0; k < N_NODES / 4 / 1024; k++)
            dst[t + 1024 * k] = src[t + 1024 * k];
    }
    __syncthreads();

    int stride = gridDim.x * blockDim.x;
    for (int e = blockIdx.x * blockDim.x + threadIdx.x; e < n_events; e += stride) {
        int p   = event_pair[e];
        int nd  = event_ndst[e];
        int off = g_evt_off[e];

        // nd in [1,4]: predicated fixed-trip loop, independent smem gathers
        float dsum = 0.0f;
        #pragma unroll
        for (int j = 0; j < 4; j++) {
            float v = (j < nd) ? s_nm[__ldg(&dst_node[off + j])] : 0.0f;
            dsum += v;
        }

        float val = s_nm[event_src[e]] + dsum / ((float)nd + 1.0f);
        red_add_v2(&g_pair[p], val, 1.0f);
    }
}

// ---------------------------------------------------------------------------
// K3: pair -> place, 2 pairs per thread (float4 / int2 loads).
//   pair_mean = (pair_sum/cnt + nm[place]) / 3
// ---------------------------------------------------------------------------
__global__ void k_pair_to_place(const int* __restrict__ pair_place) {
    int t = blockIdx.x * blockDim.x + threadIdx.x;
    if (t >= N_PAIRS / 2) return;
    float4 a = reinterpret_cast<const float4*>(g_pair)[t];     // pairs 2t, 2t+1
    int2 pl = reinterpret_cast<const int2*>(pair_place)[t];
    if (a.y > 0.0f) {
        float pm = (a.x / a.y + __ldg(&g_node_mean[pl.x])) * (1.0f / 3.0f);
        red_add_v2(&g_place[pl.x], pm, 1.0f);
    }
    if (a.w > 0.0f) {
        float pm = (a.z / a.w + __ldg(&g_node_mean[pl.y])) * (1.0f / 3.0f);
        red_add_v2(&g_place[pl.y], pm, 1.0f);
    }
}

// ---------------------------------------------------------------------------
// K4: broadcast fill — one warp per row, 12 independent STG.128 per lane.
//     At the chip STG/LTS cap (~6.1TB/s); this is the floor.
// ---------------------------------------------------------------------------
__global__ void k_fill_out(float* __restrict__ out) {
    int tid = blockIdx.x * blockDim.x + threadIdx.x;
    int row = tid >> 5;
    int lane = tid & 31;
    float2 a = g_place[row];          // same addr across warp -> broadcast
    float v = (a.y > 0.0f) ? (a.x / a.y) : 0.0f;
    float4 v4 = make_float4(v, v, v, v);
    float4* o = reinterpret_cast<float4*>(out + (size_t)row * (3 * EMB));
    #pragma unroll
    for (int k = 0; k < 12; k++)
        o[lane + 32 * k] = v4;
}

// ---------------------------------------------------------------------------
extern "C" void kernel_launch(void* const* d_in, const int* in_sizes, int n_in,
                              void* d_out, int out_size) {
    const float* embeddings = (const float*)d_in[0];
    const int* pair_place   = (const int*)d_in[1];
    const int* event_pair   = (const int*)d_in[2];
    const int* event_src    = (const int*)d_in[3];
    const int* event_ndst   = (const int*)d_in[4];
    const int* dst_event    = (const int*)d_in[5];
    const int* dst_node     = (const int*)d_in[6];
    float* out = (float*)d_out;

    int n_events = in_sizes[2];
    int n_dst = in_sizes[5];

    const int SMEM = N_NODES * (int)sizeof(float);   // 64KB
    cudaFuncSetAttribute(k_event_scatter,
                         cudaFuncAttributeMaxDynamicSharedMemorySize, SMEM);

    k_prep<<<2048, 256>>>(embeddings, dst_event, n_dst);
    k_event_scatter<<<296, 1024, SMEM>>>(event_pair, event_src, event_ndst,
                                         dst_node, n_events);
    k_pair_to_place<<<(N_PAIRS / 2 + 255) / 256, 256>>>(pair_place);
    k_fill_out<<<2048, 256>>>(out);
}